// round 5
// baseline (speedup 1.0000x reference)
#include <cuda_runtime.h>
#include <math.h>
#include <stdint.h>

#define B   8
#define N   4096
#define F   64
#define M   2048
#define KNB 32
#define H1  64
#define H2  128
#define R2  0.04f
#define CAP 512

#define OUT_OFF   0
#define POSS_OFF  (B*M*H2)             // 2097152
#define NORMS_OFF (POSS_OFF + B*M*3)   // 2146304

// ---------------- scratch (no allocations allowed) ----------------
__device__ int   g_idx[B*M];
__device__ float g_y[(size_t)B*N*H1];
__device__ int   g_nbr[B*M*KNB];
__device__ int   g_cnt[B*M];

// ---------------- packed f32x2 helpers (sm_103a) ----------------
__device__ __forceinline__ uint64_t pk2(float lo, float hi) {
    uint64_t r;
    asm("mov.b64 %0, {%1, %2};" : "=l"(r)
        : "r"(__float_as_uint(lo)), "r"(__float_as_uint(hi)));
    return r;
}
__device__ __forceinline__ void upk2(float& lo, float& hi, uint64_t v) {
    unsigned a, b;
    asm("mov.b64 {%0, %1}, %2;" : "=r"(a), "=r"(b) : "l"(v));
    lo = __uint_as_float(a); hi = __uint_as_float(b);
}
__device__ __forceinline__ uint64_t add2(uint64_t a, uint64_t b) {
    uint64_t d; asm("add.rn.f32x2 %0, %1, %2;" : "=l"(d) : "l"(a), "l"(b)); return d;
}
__device__ __forceinline__ uint64_t mul2(uint64_t a, uint64_t b) {
    uint64_t d; asm("mul.rn.f32x2 %0, %1, %2;" : "=l"(d) : "l"(a), "l"(b)); return d;
}
__device__ __forceinline__ uint64_t fma2(uint64_t a, uint64_t b, uint64_t c) {
    uint64_t d; asm("fma.rn.f32x2 %0, %1, %2, %3;" : "=l"(d) : "l"(a), "l"(b), "l"(c)); return d;
}

// Exact-order |p|^2 matching XLA's uncontracted emission:
// ((x*x + y*y) + z*z), each op individually rounded, no FMA.
__device__ __forceinline__ float sum3sq_exact(float x, float y, float z)
{
    float a = __fmul_rn(x, x);
    float b = __fmul_rn(y, y);
    float c = __fmul_rn(z, z);
    return __fadd_rn(__fadd_rn(a, b), c);
}

// =============================================================
// Kernel 1: farthest point sampling. One block per batch.
// Packed f32x2 math, bit-identical per lane to the scalar
// intrinsic sequence (sub==add-of-neg, separate mul/add, XLA
// association order). Single barrier per iteration via parity-
// double-buffered warp partials + redundant final reduction in
// every warp (reads via LDS broadcast).
// =============================================================
extern "C" __global__ void __launch_bounds__(512, 1)
fps_kernel(const float* __restrict__ pos)
{
    extern __shared__ float fsm[];
    float* spx = fsm;
    float* spy = fsm + N;
    float* spz = fsm + 2*N;
    __shared__ unsigned s_wval[2][16];
    __shared__ unsigned s_widx[2][16];

    const int b = blockIdx.x;
    const float* pb = pos + (size_t)b*N*3;
    const int t = threadIdx.x;

    for (int i = t; i < N; i += 512) {
        float x = pb[3*i+0], y = pb[3*i+1], z = pb[3*i+2];
        spx[i] = x; spy[i] = y; spz[i] = z;
    }
    if (t == 0) g_idx[b*M] = 0;
    float dmin[8];
#pragma unroll
    for (int j = 0; j < 8; j++) dmin[j] = 3.4e38f;
    __syncthreads();

    const int lane = t & 31, wid = t >> 5;
    float lx = spx[0], ly = spy[0], lz = spz[0];
    int p = 0;

    for (int i = 1; i < M; i++) {
        const uint64_t nlx = pk2(-lx, -lx);
        const uint64_t nly = pk2(-ly, -ly);
        const uint64_t nlz = pk2(-lz, -lz);
        float lmax = -1.0f; int lidx = 0;
#pragma unroll
        for (int g = 0; g < 2; g++) {
            const int base = 4*t + 2048*g;
            ulonglong2 X = reinterpret_cast<const ulonglong2*>(spx)[t + 512*g];
            ulonglong2 Y = reinterpret_cast<const ulonglong2*>(spy)[t + 512*g];
            ulonglong2 Z = reinterpret_cast<const ulonglong2*>(spz)[t + 512*g];
            {
                uint64_t dx = add2(X.x, nlx);
                uint64_t dy = add2(Y.x, nly);
                uint64_t dz = add2(Z.x, nlz);
                uint64_t s  = add2(add2(mul2(dx,dx), mul2(dy,dy)), mul2(dz,dz));
                float d0, d1; upk2(d0, d1, s);
                float m0 = fminf(dmin[4*g+0], d0); dmin[4*g+0] = m0;
                if (m0 > lmax) { lmax = m0; lidx = base+0; }
                float m1 = fminf(dmin[4*g+1], d1); dmin[4*g+1] = m1;
                if (m1 > lmax) { lmax = m1; lidx = base+1; }
            }
            {
                uint64_t dx = add2(X.y, nlx);
                uint64_t dy = add2(Y.y, nly);
                uint64_t dz = add2(Z.y, nlz);
                uint64_t s  = add2(add2(mul2(dx,dx), mul2(dy,dy)), mul2(dz,dz));
                float d0, d1; upk2(d0, d1, s);
                float m0 = fminf(dmin[4*g+2], d0); dmin[4*g+2] = m0;
                if (m0 > lmax) { lmax = m0; lidx = base+2; }
                float m1 = fminf(dmin[4*g+3], d1); dmin[4*g+3] = m1;
                if (m1 > lmax) { lmax = m1; lidx = base+3; }
            }
        }
        // warp-level argmax, lowest-index tie-break (dmin >= 0 so
        // float bits are order-isomorphic to u32)
        unsigned bv   = __float_as_uint(lmax);
        unsigned wmax = __reduce_max_sync(0xffffffffu, bv);
        unsigned cand = (bv == wmax) ? (unsigned)lidx : 0xffffffffu;
        unsigned widx = __reduce_min_sync(0xffffffffu, cand);
        if (lane == 0) { s_wval[p][wid] = wmax; s_widx[p][wid] = widx; }
        __syncthreads();
        // every warp redundantly reduces the 16 partials
        unsigned v  = (lane < 16) ? s_wval[p][lane] : 0u;
        unsigned ci = (lane < 16) ? s_widx[p][lane] : 0xffffffffu;
        unsigned gm = __reduce_max_sync(0xffffffffu, v);
        unsigned gc = (v == gm) ? ci : 0xffffffffu;
        unsigned gi = __reduce_min_sync(0xffffffffu, gc);
        lx = spx[gi]; ly = spy[gi]; lz = spz[gi];   // LDS broadcast
        if (t == 0) g_idx[b*M + i] = (int)gi;
        p ^= 1;
    }
}

// =============================================================
// Kernel 2: y = x @ W1[:64] + b1   (per-point, factored layer 1)
// =============================================================
extern "C" __global__ void __launch_bounds__(256)
y_kernel(const float* __restrict__ x, const float* __restrict__ W1,
         const float* __restrict__ b1)
{
    __shared__ float W1s[64*64];
    __shared__ float xs[4][64];
    const int t = threadIdx.x;
    for (int i = t; i < 64*64; i += 256) W1s[i] = W1[i];
    const int g = t >> 6, c = t & 63;
    const int row = blockIdx.x*4 + g;        // row in [0, B*N)
    xs[g][c] = x[(size_t)row*64 + c];
    __syncthreads();
    float acc = b1[c];
#pragma unroll 8
    for (int f = 0; f < 64; f++)
        acc = fmaf(xs[g][f], W1s[f*64 + c], acc);
    g_y[(size_t)row*64 + c] = acc;
}

// =============================================================
// Kernel 3: gather pos_s / norm_s into the output buffer
// =============================================================
extern "C" __global__ void gather_kernel(const float* __restrict__ pos,
                                         const float* __restrict__ norm,
                                         float* __restrict__ outbuf)
{
    int i = blockIdx.x*256 + threadIdx.x;
    if (i >= B*M) return;
    int b = i / M;
    int j = g_idx[i];
    const float* p  = pos  + ((size_t)b*N + j)*3;
    const float* nr = norm + ((size_t)b*N + j)*3;
    outbuf[POSS_OFF  + i*3 + 0] = p[0];
    outbuf[POSS_OFF  + i*3 + 1] = p[1];
    outbuf[POSS_OFF  + i*3 + 2] = p[2];
    outbuf[NORMS_OFF + i*3 + 0] = nr[0];
    outbuf[NORMS_OFF + i*3 + 1] = nr[1];
    outbuf[NORMS_OFF + i*3 + 2] = nr[2];
}

// =============================================================
// Kernel 4: neighbor selection. Warp per center; filter by R^2
// then extract the <=32 smallest d2. d2 in the reference's exact
// expansion/order: (si + sj) - 2*dot, all ops individually rounded.
// Selected SET (not order) is what the masked max consumes, so
// only boundary ties matter; (d2, lowest-index) extraction
// matches lax.top_k's tie rule.
// =============================================================
extern "C" __global__ void __launch_bounds__(256)
select_kernel(const float* __restrict__ pos, const float* __restrict__ outbuf)
{
    extern __shared__ float4 sp4[];                  // N float4 = 64 KB
    float* cd = (float*)(sp4 + N);                   // 8*CAP floats
    int*   ci = (int*)(cd + 8*CAP);                  // 8*CAP ints
    __shared__ int scnt[8];

    const int t = threadIdx.x;
    const int b  = blockIdx.x >> 8;                  // 256 blocks per batch
    const int m0 = (blockIdx.x & 255) * 8;
    const float* pb = pos + (size_t)b*N*3;

    for (int i = t; i < N; i += 256) {
        float x = pb[3*i+0], y = pb[3*i+1], z = pb[3*i+2];
        sp4[i] = make_float4(x, y, z, sum3sq_exact(x, y, z));
    }
    const int w = t >> 5, lane = t & 31;
    if (lane == 0) scnt[w] = 0;
    __syncthreads();

    const int m = m0 + w;
    const int gid = b*M + m;
    const float cx = outbuf[POSS_OFF + gid*3 + 0];
    const float cy = outbuf[POSS_OFF + gid*3 + 1];
    const float cz = outbuf[POSS_OFF + gid*3 + 2];
    const float si = sum3sq_exact(cx, cy, cz);

    float* mycd = cd + w*CAP;
    int*   myci = ci + w*CAP;

    for (int p = lane; p < N; p += 32) {
        float4 P = sp4[p];
        float dot = __fadd_rn(__fadd_rn(__fmul_rn(cx, P.x), __fmul_rn(cy, P.y)),
                              __fmul_rn(cz, P.z));
        float d2 = __fsub_rn(__fadd_rn(si, P.w), __fmul_rn(2.0f, dot));
        if (d2 <= R2) {
            int slot = atomicAdd(&scnt[w], 1);
            if (slot < CAP) { mycd[slot] = d2; myci[slot] = p; }
        }
    }
    __syncwarp();
    int cnt = scnt[w]; if (cnt > CAP) cnt = CAP;

    if (cnt <= KNB) {
        for (int s = lane; s < cnt; s += 32)
            g_nbr[gid*KNB + s] = myci[s];
        if (lane == 0) g_cnt[gid] = cnt;
    } else {
        for (int r = 0; r < KNB; r++) {
            float bvv = 3.4e38f; int bslot = -1;
            for (int s = lane; s < cnt; s += 32) {
                float v = mycd[s];
                if (v < bvv) { bvv = v; bslot = s; }
            }
            unsigned wmin = __reduce_min_sync(0xffffffffu, __float_as_uint(bvv));
            int pidx = (__float_as_uint(bvv) == wmin && bslot >= 0)
                         ? myci[bslot] : 0x7fffffff;
            int widx = (int)__reduce_min_sync(0xffffffffu, (unsigned)pidx);
            if (pidx == widx && bslot >= 0) mycd[bslot] = 3.4e38f;
            if (lane == 0) g_nbr[gid*KNB + r] = widx;
            __syncwarp();
        }
        if (lane == 0) g_cnt[gid] = KNB;
    }
}

// =============================================================
// Kernel 5: fused PPF + layer1-residual + layer2 + masked max.
// h1 stored TRANSPOSED (h1t[f][k], stride 34) so neighbor pairs
// load as u64 broadcasts (warp-uniform, conflict-free); layer 2
// uses fma.rn.f32x2 (FFMA2) pairing over neighbors.
// relu(max)==max(relu) defers b2+relu past the k-max.
// =============================================================
__device__ __forceinline__ float get_angle(float ax, float ay, float az,
                                           float bx, float by, float bz)
{
    float cxv = ay*bz - az*by;
    float cyv = az*bx - ax*bz;
    float czv = ax*by - ay*bx;
    float cn  = sqrtf(cxv*cxv + cyv*cyv + czv*czv);
    float d   = ax*bx + ay*by + az*bz;
    if (cn == 0.0f && d == 0.0f) d = 1.0f;
    return atan2f(cn, d);
}

extern "C" __global__ void __launch_bounds__(128)
mlp_kernel(const float* __restrict__ pos, const float* __restrict__ norm,
           const float* __restrict__ W1, const float* __restrict__ W2,
           const float* __restrict__ b2, float* __restrict__ outbuf)
{
    __shared__ float W2s[64*128];     // 32 KB
    __shared__ float b2s[128];
    __shared__ float W1bs[4*64];      // W1 rows 64..67
    __shared__ float h1t[64*34];      // transposed: h1t[f*34 + k]
    __shared__ float pm[4*128];
    __shared__ int   snbr[32];
    __shared__ int   scnt_s;
    __shared__ float scen[6];

    const int t = threadIdx.x;
    for (int i = t; i < 64*128; i += 128) W2s[i] = W2[i];
    b2s[t & 127] = b2[t & 127];
    for (int i = t; i < 256; i += 128) W1bs[i] = W1[64*64 + i];

    for (int cblk = 0; cblk < 8; cblk++) {
        const int gid = blockIdx.x*8 + cblk;
        const int b = gid / M;
        __syncthreads();   // protect smem reuse across centers
        if (t < 32) snbr[t] = g_nbr[gid*KNB + t];
        if (t == 32) scnt_s = g_cnt[gid];
        if (t >= 40 && t < 43) scen[t-40]     = outbuf[POSS_OFF  + gid*3 + (t-40)];
        if (t >= 43 && t < 46) scen[3 + t-43] = outbuf[NORMS_OFF + gid*3 + (t-43)];
        __syncthreads();
        const int cnt = scnt_s;

        // ---- edge phase: h1t[f][k] = relu(y_j[f] + ppf . W1b[:,f]) ----
        {
            const int k = t >> 2, q = t & 3;
            const int j = (k < cnt) ? snbr[k] : 0;
            const float* pj = pos  + ((size_t)b*N + j)*3;
            const float* nj = norm + ((size_t)b*N + j)*3;
            float px = pj[0], py = pj[1], pz = pj[2];
            float nx = nj[0], ny = nj[1], nz = nj[2];
            float cxp = scen[0], cyp = scen[1], czp = scen[2];
            float nix = scen[3], niy = scen[4], niz = scen[5];
            float dx = px - cxp, dy = py - cyp, dz = pz - czp;
            float f0 = sqrtf(dx*dx + dy*dy + dz*dz);
            float f1 = get_angle(nix, niy, niz, dx, dy, dz);
            float f2 = get_angle(nx,  ny,  nz,  dx, dy, dz);
            float f3 = get_angle(nix, niy, niz, nx, ny, nz);
            const float* yrow = g_y + ((size_t)b*N + j)*64 + q*16;
#pragma unroll
            for (int u = 0; u < 16; u++) {
                int f = q*16 + u;
                float v = yrow[u];
                v = fmaf(f0, W1bs[f],       v);
                v = fmaf(f1, W1bs[64  + f], v);
                v = fmaf(f2, W1bs[128 + f], v);
                v = fmaf(f3, W1bs[192 + f], v);
                h1t[f*34 + k] = fmaxf(v, 0.0f);
            }
        }
        __syncthreads();

        // ---- layer 2 (FFMA2): acc[(e,e+1)][c] += h_pair * (w_c,w_c) ----
        {
            const int kq = t >> 5, cg = t & 31;
            uint64_t accp[4][4];
#pragma unroll
            for (int ep = 0; ep < 4; ep++)
#pragma unroll
                for (int c = 0; c < 4; c++) accp[ep][c] = 0ull;

#pragma unroll 2
            for (int f = 0; f < 64; f++) {
                const float* hb = &h1t[f*34 + kq*8];
                uint64_t h0 = *reinterpret_cast<const uint64_t*>(hb + 0);
                uint64_t h1 = *reinterpret_cast<const uint64_t*>(hb + 2);
                uint64_t h2 = *reinterpret_cast<const uint64_t*>(hb + 4);
                uint64_t h3 = *reinterpret_cast<const uint64_t*>(hb + 6);
                float4 wv = *reinterpret_cast<const float4*>(&W2s[f*128 + cg*4]);
                uint64_t w0 = pk2(wv.x, wv.x);
                uint64_t w1 = pk2(wv.y, wv.y);
                uint64_t w2 = pk2(wv.z, wv.z);
                uint64_t w3 = pk2(wv.w, wv.w);
                accp[0][0] = fma2(h0, w0, accp[0][0]);
                accp[0][1] = fma2(h0, w1, accp[0][1]);
                accp[0][2] = fma2(h0, w2, accp[0][2]);
                accp[0][3] = fma2(h0, w3, accp[0][3]);
                accp[1][0] = fma2(h1, w0, accp[1][0]);
                accp[1][1] = fma2(h1, w1, accp[1][1]);
                accp[1][2] = fma2(h1, w2, accp[1][2]);
                accp[1][3] = fma2(h1, w3, accp[1][3]);
                accp[2][0] = fma2(h2, w0, accp[2][0]);
                accp[2][1] = fma2(h2, w1, accp[2][1]);
                accp[2][2] = fma2(h2, w2, accp[2][2]);
                accp[2][3] = fma2(h2, w3, accp[2][3]);
                accp[3][0] = fma2(h3, w0, accp[3][0]);
                accp[3][1] = fma2(h3, w1, accp[3][1]);
                accp[3][2] = fma2(h3, w2, accp[3][2]);
                accp[3][3] = fma2(h3, w3, accp[3][3]);
            }
            float v0 = -3.4e38f, v1 = -3.4e38f, v2 = -3.4e38f, v3 = -3.4e38f;
#pragma unroll
            for (int ep = 0; ep < 4; ep++) {
                const int e0 = kq*8 + 2*ep;
                float a, bb;
                upk2(a, bb, accp[ep][0]);
                if (e0     < cnt) v0 = fmaxf(v0, a);
                if (e0 + 1 < cnt) v0 = fmaxf(v0, bb);
                upk2(a, bb, accp[ep][1]);
                if (e0     < cnt) v1 = fmaxf(v1, a);
                if (e0 + 1 < cnt) v1 = fmaxf(v1, bb);
                upk2(a, bb, accp[ep][2]);
                if (e0     < cnt) v2 = fmaxf(v2, a);
                if (e0 + 1 < cnt) v2 = fmaxf(v2, bb);
                upk2(a, bb, accp[ep][3]);
                if (e0     < cnt) v3 = fmaxf(v3, a);
                if (e0 + 1 < cnt) v3 = fmaxf(v3, bb);
            }
            *reinterpret_cast<float4*>(&pm[kq*128 + cg*4]) =
                make_float4(v0, v1, v2, v3);
        }
        __syncthreads();

        // ---- combine 4 k-groups, add b2, relu, store ----
        {
            const int c = t;
            float v = fmaxf(fmaxf(pm[c], pm[128 + c]),
                            fmaxf(pm[256 + c], pm[384 + c]));
            float r = fmaxf(v + b2s[c], 0.0f);
            outbuf[(size_t)gid*128 + c] = r;
        }
    }
}

// =============================================================
extern "C" void kernel_launch(void* const* d_in, const int* in_sizes, int n_in,
                              void* d_out, int out_size)
{
    const float* x    = (const float*)d_in[0];
    const float* pos  = (const float*)d_in[1];
    const float* norm = (const float*)d_in[2];
    const float* W1   = (const float*)d_in[3];
    const float* b1   = (const float*)d_in[4];
    const float* W2   = (const float*)d_in[5];
    const float* b2   = (const float*)d_in[6];
    float* out = (float*)d_out;

    (void)in_sizes; (void)n_in; (void)out_size;

    cudaFuncSetAttribute(fps_kernel,
        cudaFuncAttributeMaxDynamicSharedMemorySize, 3*N*4);
    size_t sel_smem = (size_t)N*16 + (size_t)8*CAP*8;
    cudaFuncSetAttribute(select_kernel,
        cudaFuncAttributeMaxDynamicSharedMemorySize, (int)sel_smem);

    fps_kernel<<<B, 512, 3*N*4>>>(pos);
    y_kernel<<<B*N/4, 256>>>(x, W1, b1);
    gather_kernel<<<(B*M + 255)/256, 256>>>(pos, norm, out);
    select_kernel<<<B*M/8, 256, sel_smem>>>(pos, out);
    mlp_kernel<<<B*M/8, 128>>>(pos, norm, W1, W2, b2, out);
}

// round 6
// speedup vs baseline: 1.0736x; 1.0736x over previous
#include <cuda_runtime.h>
#include <math.h>
#include <stdint.h>

#define B    8
#define N    4096
#define F    64
#define M    2048
#define KNB  32
#define H1   64
#define H2   128
#define R2   0.04f
#define CAP2 256

#define OUT_OFF   0
#define POSS_OFF  (B*M*H2)             // 2097152
#define NORMS_OFF (POSS_OFF + B*M*3)   // 2146304

// ---------------- scratch (no allocations allowed) ----------------
__device__ int    g_idx[B*M];
__device__ float  g_y[(size_t)B*N*H1];
__device__ int    g_nbr[B*M*KNB];
__device__ int    g_cnt[B*M];
__device__ float4 g_p4[B*N];

// ---------------- packed f32x2 helpers (sm_103a) ----------------
__device__ __forceinline__ uint64_t pk2(float lo, float hi) {
    uint64_t r;
    asm("mov.b64 %0, {%1, %2};" : "=l"(r)
        : "r"(__float_as_uint(lo)), "r"(__float_as_uint(hi)));
    return r;
}
__device__ __forceinline__ void upk2(float& lo, float& hi, uint64_t v) {
    unsigned a, b;
    asm("mov.b64 {%0, %1}, %2;" : "=r"(a), "=r"(b) : "l"(v));
    lo = __uint_as_float(a); hi = __uint_as_float(b);
}
__device__ __forceinline__ uint64_t fma2(uint64_t a, uint64_t b, uint64_t c) {
    uint64_t d; asm("fma.rn.f32x2 %0, %1, %2, %3;" : "=l"(d) : "l"(a), "l"(b), "l"(c)); return d;
}

// FROZEN: exact-order distance math matching XLA's uncontracted
// emission. Do not change (validated pass at rel_err 6.8e-4).
__device__ __forceinline__ float d2_exact(float px, float py, float pz,
                                          float lx, float ly, float lz)
{
    float dx = __fsub_rn(px, lx);
    float dy = __fsub_rn(py, ly);
    float dz = __fsub_rn(pz, lz);
    float a  = __fmul_rn(dx, dx);
    float b  = __fmul_rn(dy, dy);
    float c  = __fmul_rn(dz, dz);
    return __fadd_rn(__fadd_rn(a, b), c);
}
__device__ __forceinline__ float sum3sq_exact(float x, float y, float z)
{
    float a = __fmul_rn(x, x);
    float b = __fmul_rn(y, y);
    float c = __fmul_rn(z, z);
    return __fadd_rn(__fadd_rn(a, b), c);
}

// =============================================================
// Kernel 1: FPS with spatial-sort + per-thread bbox pruning.
// Counting-sort into 4x4x4 grid cells (points spatially tight per
// thread); thread caches (max dmin, packed argmax). Skip condition
// mindist(bbox,c)^2 * 0.999 > threadmax guarantees every skipped
// update is min(dmin, larger-value) == no-op -> dmin bit-identical
// to the unpruned version. Tie-break on ORIGINAL index (packed).
// =============================================================
extern "C" __global__ void __launch_bounds__(512, 1)
fps_kernel(const float* __restrict__ pos)
{
    extern __shared__ float fsm[];
    float* spx  = fsm;              // N
    float* spy  = fsm + N;          // N
    float* spz  = fsm + 2*N;        // N
    int*   sidx = (int*)(fsm + 3*N);// N
    __shared__ int hist[64];
    __shared__ int offs[64];
    __shared__ unsigned s_wval[2][16];
    __shared__ unsigned s_wpay[2][16];

    const int b = blockIdx.x;
    const float* pb = pos + (size_t)b*N*3;
    const int t = threadIdx.x;
    const int lane = t & 31, wid = t >> 5;

    if (t < 64) hist[t] = 0;
    __syncthreads();
    // pass 1: histogram of 4x4x4 cells (pos uniform in [0,1))
    for (int i = t; i < N; i += 512) {
        float x = pb[3*i], y = pb[3*i+1], z = pb[3*i+2];
        int cx = min(3, (int)(x*4.0f));
        int cy = min(3, (int)(y*4.0f));
        int cz = min(3, (int)(z*4.0f));
        atomicAdd(&hist[cx*16 + cy*4 + cz], 1);
    }
    __syncthreads();
    if (t == 0) {
        int run = 0;
        for (int c = 0; c < 64; c++) { offs[c] = run; run += hist[c]; }
    }
    __syncthreads();
    // pass 2: scatter (within-cell order nondeterministic but the
    // computed dmin/argmax are layout-independent)
    for (int i = t; i < N; i += 512) {
        float x = pb[3*i], y = pb[3*i+1], z = pb[3*i+2];
        int cx = min(3, (int)(x*4.0f));
        int cy = min(3, (int)(y*4.0f));
        int cz = min(3, (int)(z*4.0f));
        int slot = atomicAdd(&offs[cx*16 + cy*4 + cz], 1);
        spx[slot] = x; spy[slot] = y; spz[slot] = z; sidx[slot] = i;
    }
    if (t == 0) g_idx[b*M] = 0;
    __syncthreads();

    // thread-local 8 sorted points in registers + bbox
    const int base = 8*t;
    float rx[8], ry[8], rz[8], dmin[8];
    unsigned plow[8];
#pragma unroll
    for (int u = 0; u < 8; u++) {
        rx[u] = spx[base+u]; ry[u] = spy[base+u]; rz[u] = spz[base+u];
        unsigned oidx = (unsigned)sidx[base+u];
        plow[u] = ((oidx ^ 0xfffu) << 12) | (unsigned)(base + u);
        dmin[u] = 3.4e38f;
    }
    float blx = rx[0], bhx = rx[0], bly = ry[0], bhy = ry[0], blz = rz[0], bhz = rz[0];
#pragma unroll
    for (int u = 1; u < 8; u++) {
        blx = fminf(blx, rx[u]); bhx = fmaxf(bhx, rx[u]);
        bly = fminf(bly, ry[u]); bhy = fmaxf(bhy, ry[u]);
        blz = fminf(blz, rz[u]); bhz = fmaxf(bhz, rz[u]);
    }

    float lx = pb[0], ly = pb[1], lz = pb[2];
    float tmaxf = 3.4e38f;
    unsigned tbits = 0u, tpay = 0xffffffffu;
    int p = 0;

    for (int i = 1; i < M; i++) {
        // conservative lower bound on distance(center, bbox)^2
        float ddx = fmaxf(fmaxf(blx - lx, lx - bhx), 0.0f);
        float ddy = fmaxf(fmaxf(bly - ly, ly - bhy), 0.0f);
        float ddz = fmaxf(fmaxf(blz - lz, lz - bhz), 0.0f);
        float m2  = ddx*ddx + ddy*ddy + ddz*ddz;
        if (!(m2 * 0.999f > tmaxf)) {
            unsigned long long best = 0ull;
#pragma unroll
            for (int u = 0; u < 8; u++) {
                float d = d2_exact(rx[u], ry[u], rz[u], lx, ly, lz);
                float m = fminf(dmin[u], d); dmin[u] = m;
                unsigned long long cand =
                    ((unsigned long long)__float_as_uint(m) << 24) | plow[u];
                best = (cand > best) ? cand : best;
            }
            tbits = (unsigned)(best >> 24);
            unsigned oidx = (((unsigned)(best >> 12)) & 0xfffu) ^ 0xfffu;
            tpay  = (oidx << 12) | ((unsigned)best & 0xfffu);
            tmaxf = __uint_as_float(tbits);
        }
        // warp argmax (max dbits, then min original index)
        unsigned wmax = __reduce_max_sync(0xffffffffu, tbits);
        unsigned pc   = (tbits == wmax) ? tpay : 0xffffffffu;
        unsigned wpay = __reduce_min_sync(0xffffffffu, pc);
        if (lane == 0) { s_wval[p][wid] = wmax; s_wpay[p][wid] = wpay; }
        __syncthreads();
        unsigned v   = (lane < 16) ? s_wval[p][lane] : 0u;
        unsigned pv  = (lane < 16) ? s_wpay[p][lane] : 0xffffffffu;
        unsigned gm  = __reduce_max_sync(0xffffffffu, v);
        unsigned gpc = (v == gm) ? pv : 0xffffffffu;
        unsigned gp  = __reduce_min_sync(0xffffffffu, gpc);
        int slot = (int)(gp & 0xfffu);
        lx = spx[slot]; ly = spy[slot]; lz = spz[slot];
        if (t == 0) g_idx[b*M + i] = (int)(gp >> 12);
        p ^= 1;
    }
}

// =============================================================
// Kernel 2: y = x @ W1[:64] + b1   (per-point, factored layer 1)
// =============================================================
extern "C" __global__ void __launch_bounds__(256)
y_kernel(const float* __restrict__ x, const float* __restrict__ W1,
         const float* __restrict__ b1)
{
    __shared__ float W1s[64*64];
    __shared__ float xs[4][64];
    const int t = threadIdx.x;
    for (int i = t; i < 64*64; i += 256) W1s[i] = W1[i];
    const int g = t >> 6, c = t & 63;
    const int row = blockIdx.x*4 + g;
    xs[g][c] = x[(size_t)row*64 + c];
    __syncthreads();
    float acc = b1[c];
#pragma unroll 8
    for (int f = 0; f < 64; f++)
        acc = fmaf(xs[g][f], W1s[f*64 + c], acc);
    g_y[(size_t)row*64 + c] = acc;
}

// =============================================================
// Kernel 3: pack (x,y,z,|p|^2) for the select scan (exact w)
// =============================================================
extern "C" __global__ void p4_kernel(const float* __restrict__ pos)
{
    int i = blockIdx.x*256 + threadIdx.x;
    if (i >= B*N) return;
    float x = pos[3*i], y = pos[3*i+1], z = pos[3*i+2];
    g_p4[i] = make_float4(x, y, z, sum3sq_exact(x, y, z));
}

// =============================================================
// Kernel 4: gather pos_s / norm_s into the output buffer
// =============================================================
extern "C" __global__ void gather_kernel(const float* __restrict__ pos,
                                         const float* __restrict__ norm,
                                         float* __restrict__ outbuf)
{
    int i = blockIdx.x*256 + threadIdx.x;
    if (i >= B*M) return;
    int b = i / M;
    int j = g_idx[i];
    const float* p  = pos  + ((size_t)b*N + j)*3;
    const float* nr = norm + ((size_t)b*N + j)*3;
    outbuf[POSS_OFF  + i*3 + 0] = p[0];
    outbuf[POSS_OFF  + i*3 + 1] = p[1];
    outbuf[POSS_OFF  + i*3 + 2] = p[2];
    outbuf[NORMS_OFF + i*3 + 0] = nr[0];
    outbuf[NORMS_OFF + i*3 + 1] = nr[1];
    outbuf[NORMS_OFF + i*3 + 2] = nr[2];
}

// =============================================================
// Kernel 5: neighbor selection. 4 centers per warp over one L2
// stream of g_p4 (no per-block cloud tile -> higher occupancy).
// d2 in the FROZEN reference order: (si + sj) - 2*dot.
// =============================================================
extern "C" __global__ void __launch_bounds__(256)
select_kernel(const float* __restrict__ outbuf)
{
    extern __shared__ float ssm[];
    float* cd = ssm;                        // 32*CAP2 floats
    int*   ci = (int*)(cd + 32*CAP2);       // 32*CAP2 ints
    __shared__ int scnt[32];

    const int t = threadIdx.x;
    const int w = t >> 5, lane = t & 31;
    const int gid0 = blockIdx.x*32 + w*4;   // 32 centers/block, same batch
    const int b = gid0 / M;

    if (t < 32) scnt[t] = 0;
    __syncthreads();

    float cx[4], cy[4], cz[4], si[4];
#pragma unroll
    for (int c = 0; c < 4; c++) {
        int gid = gid0 + c;
        cx[c] = outbuf[POSS_OFF + gid*3 + 0];
        cy[c] = outbuf[POSS_OFF + gid*3 + 1];
        cz[c] = outbuf[POSS_OFF + gid*3 + 2];
        si[c] = sum3sq_exact(cx[c], cy[c], cz[c]);
    }
    const float4* pp = g_p4 + (size_t)b*N;

#pragma unroll 2
    for (int p = lane; p < N; p += 32) {
        float4 P = __ldg(&pp[p]);
#pragma unroll
        for (int c = 0; c < 4; c++) {
            float dot = __fadd_rn(__fadd_rn(__fmul_rn(cx[c], P.x),
                                            __fmul_rn(cy[c], P.y)),
                                  __fmul_rn(cz[c], P.z));
            float d2 = __fsub_rn(__fadd_rn(si[c], P.w), __fmul_rn(2.0f, dot));
            if (d2 <= R2) {
                int wc = w*4 + c;
                int slot = atomicAdd(&scnt[wc], 1);
                if (slot < CAP2) { cd[wc*CAP2 + slot] = d2; ci[wc*CAP2 + slot] = p; }
            }
        }
    }
    __syncwarp();

#pragma unroll 1
    for (int c = 0; c < 4; c++) {
        const int wc = w*4 + c;
        const int gid = gid0 + c;
        int cnt = scnt[wc]; if (cnt > CAP2) cnt = CAP2;
        float* mycd = cd + wc*CAP2;
        int*   myci = ci + wc*CAP2;

        if (cnt <= KNB) {
            for (int s = lane; s < cnt; s += 32)
                g_nbr[gid*KNB + s] = myci[s];
            if (lane == 0) g_cnt[gid] = cnt;
        } else {
            for (int r = 0; r < KNB; r++) {
                float bvv = 3.4e38f; int bslot = -1;
                for (int s = lane; s < cnt; s += 32) {
                    float v = mycd[s];
                    if (v < bvv) { bvv = v; bslot = s; }
                }
                unsigned wmin = __reduce_min_sync(0xffffffffu, __float_as_uint(bvv));
                int pidx = (__float_as_uint(bvv) == wmin && bslot >= 0)
                             ? myci[bslot] : 0x7fffffff;
                int widx = (int)__reduce_min_sync(0xffffffffu, (unsigned)pidx);
                if (pidx == widx && bslot >= 0) mycd[bslot] = 3.4e38f;
                if (lane == 0) g_nbr[gid*KNB + r] = widx;
                __syncwarp();
            }
            if (lane == 0) g_cnt[gid] = KNB;
        }
    }
}

// =============================================================
// Kernel 6: fused PPF + layer1-residual + layer2 + masked max.
// (unchanged from the validated R5 kernel)
// =============================================================
__device__ __forceinline__ float get_angle(float ax, float ay, float az,
                                           float bx, float by, float bz)
{
    float cxv = ay*bz - az*by;
    float cyv = az*bx - ax*bz;
    float czv = ax*by - ay*bx;
    float cn  = sqrtf(cxv*cxv + cyv*cyv + czv*czv);
    float d   = ax*bx + ay*by + az*bz;
    if (cn == 0.0f && d == 0.0f) d = 1.0f;
    return atan2f(cn, d);
}

extern "C" __global__ void __launch_bounds__(128)
mlp_kernel(const float* __restrict__ pos, const float* __restrict__ norm,
           const float* __restrict__ W1, const float* __restrict__ W2,
           const float* __restrict__ b2, float* __restrict__ outbuf)
{
    __shared__ float W2s[64*128];
    __shared__ float b2s[128];
    __shared__ float W1bs[4*64];
    __shared__ float h1t[64*34];
    __shared__ float pm[4*128];
    __shared__ int   snbr[32];
    __shared__ int   scnt_s;
    __shared__ float scen[6];

    const int t = threadIdx.x;
    for (int i = t; i < 64*128; i += 128) W2s[i] = W2[i];
    b2s[t & 127] = b2[t & 127];
    for (int i = t; i < 256; i += 128) W1bs[i] = W1[64*64 + i];

    for (int cblk = 0; cblk < 8; cblk++) {
        const int gid = blockIdx.x*8 + cblk;
        const int b = gid / M;
        __syncthreads();
        if (t < 32) snbr[t] = g_nbr[gid*KNB + t];
        if (t == 32) scnt_s = g_cnt[gid];
        if (t >= 40 && t < 43) scen[t-40]     = outbuf[POSS_OFF  + gid*3 + (t-40)];
        if (t >= 43 && t < 46) scen[3 + t-43] = outbuf[NORMS_OFF + gid*3 + (t-43)];
        __syncthreads();
        const int cnt = scnt_s;

        {
            const int k = t >> 2, q = t & 3;
            const int j = (k < cnt) ? snbr[k] : 0;
            const float* pj = pos  + ((size_t)b*N + j)*3;
            const float* nj = norm + ((size_t)b*N + j)*3;
            float px = pj[0], py = pj[1], pz = pj[2];
            float nx = nj[0], ny = nj[1], nz = nj[2];
            float cxp = scen[0], cyp = scen[1], czp = scen[2];
            float nix = scen[3], niy = scen[4], niz = scen[5];
            float dx = px - cxp, dy = py - cyp, dz = pz - czp;
            float f0 = sqrtf(dx*dx + dy*dy + dz*dz);
            float f1 = get_angle(nix, niy, niz, dx, dy, dz);
            float f2 = get_angle(nx,  ny,  nz,  dx, dy, dz);
            float f3 = get_angle(nix, niy, niz, nx, ny, nz);
            const float* yrow = g_y + ((size_t)b*N + j)*64 + q*16;
#pragma unroll
            for (int u = 0; u < 16; u++) {
                int f = q*16 + u;
                float v = yrow[u];
                v = fmaf(f0, W1bs[f],       v);
                v = fmaf(f1, W1bs[64  + f], v);
                v = fmaf(f2, W1bs[128 + f], v);
                v = fmaf(f3, W1bs[192 + f], v);
                h1t[f*34 + k] = fmaxf(v, 0.0f);
            }
        }
        __syncthreads();

        {
            const int kq = t >> 5, cg = t & 31;
            uint64_t accp[4][4];
#pragma unroll
            for (int ep = 0; ep < 4; ep++)
#pragma unroll
                for (int c = 0; c < 4; c++) accp[ep][c] = 0ull;

#pragma unroll 2
            for (int f = 0; f < 64; f++) {
                const float* hb = &h1t[f*34 + kq*8];
                uint64_t h0 = *reinterpret_cast<const uint64_t*>(hb + 0);
                uint64_t h1 = *reinterpret_cast<const uint64_t*>(hb + 2);
                uint64_t h2 = *reinterpret_cast<const uint64_t*>(hb + 4);
                uint64_t h3 = *reinterpret_cast<const uint64_t*>(hb + 6);
                float4 wv = *reinterpret_cast<const float4*>(&W2s[f*128 + cg*4]);
                uint64_t w0 = pk2(wv.x, wv.x);
                uint64_t w1 = pk2(wv.y, wv.y);
                uint64_t w2 = pk2(wv.z, wv.z);
                uint64_t w3 = pk2(wv.w, wv.w);
                accp[0][0] = fma2(h0, w0, accp[0][0]);
                accp[0][1] = fma2(h0, w1, accp[0][1]);
                accp[0][2] = fma2(h0, w2, accp[0][2]);
                accp[0][3] = fma2(h0, w3, accp[0][3]);
                accp[1][0] = fma2(h1, w0, accp[1][0]);
                accp[1][1] = fma2(h1, w1, accp[1][1]);
                accp[1][2] = fma2(h1, w2, accp[1][2]);
                accp[1][3] = fma2(h1, w3, accp[1][3]);
                accp[2][0] = fma2(h2, w0, accp[2][0]);
                accp[2][1] = fma2(h2, w1, accp[2][1]);
                accp[2][2] = fma2(h2, w2, accp[2][2]);
                accp[2][3] = fma2(h2, w3, accp[2][3]);
                accp[3][0] = fma2(h3, w0, accp[3][0]);
                accp[3][1] = fma2(h3, w1, accp[3][1]);
                accp[3][2] = fma2(h3, w2, accp[3][2]);
                accp[3][3] = fma2(h3, w3, accp[3][3]);
            }
            float v0 = -3.4e38f, v1 = -3.4e38f, v2 = -3.4e38f, v3 = -3.4e38f;
#pragma unroll
            for (int ep = 0; ep < 4; ep++) {
                const int e0 = kq*8 + 2*ep;
                float a, bb;
                upk2(a, bb, accp[ep][0]);
                if (e0     < cnt) v0 = fmaxf(v0, a);
                if (e0 + 1 < cnt) v0 = fmaxf(v0, bb);
                upk2(a, bb, accp[ep][1]);
                if (e0     < cnt) v1 = fmaxf(v1, a);
                if (e0 + 1 < cnt) v1 = fmaxf(v1, bb);
                upk2(a, bb, accp[ep][2]);
                if (e0     < cnt) v2 = fmaxf(v2, a);
                if (e0 + 1 < cnt) v2 = fmaxf(v2, bb);
                upk2(a, bb, accp[ep][3]);
                if (e0     < cnt) v3 = fmaxf(v3, a);
                if (e0 + 1 < cnt) v3 = fmaxf(v3, bb);
            }
            *reinterpret_cast<float4*>(&pm[kq*128 + cg*4]) =
                make_float4(v0, v1, v2, v3);
        }
        __syncthreads();

        {
            const int c = t;
            float v = fmaxf(fmaxf(pm[c], pm[128 + c]),
                            fmaxf(pm[256 + c], pm[384 + c]));
            float r = fmaxf(v + b2s[c], 0.0f);
            outbuf[(size_t)gid*128 + c] = r;
        }
    }
}

// =============================================================
extern "C" void kernel_launch(void* const* d_in, const int* in_sizes, int n_in,
                              void* d_out, int out_size)
{
    const float* x    = (const float*)d_in[0];
    const float* pos  = (const float*)d_in[1];
    const float* norm = (const float*)d_in[2];
    const float* W1   = (const float*)d_in[3];
    const float* b1   = (const float*)d_in[4];
    const float* W2   = (const float*)d_in[5];
    const float* b2   = (const float*)d_in[6];
    float* out = (float*)d_out;

    (void)in_sizes; (void)n_in; (void)out_size;

    cudaFuncSetAttribute(fps_kernel,
        cudaFuncAttributeMaxDynamicSharedMemorySize, 4*N*4);
    cudaFuncSetAttribute(select_kernel,
        cudaFuncAttributeMaxDynamicSharedMemorySize, 32*CAP2*8);

    fps_kernel<<<B, 512, 4*N*4>>>(pos);
    y_kernel<<<B*N/4, 256>>>(x, W1, b1);
    p4_kernel<<<(B*N + 255)/256, 256>>>(pos);
    gather_kernel<<<(B*M + 255)/256, 256>>>(pos, norm, out);
    select_kernel<<<B*M/32, 256, 32*CAP2*8>>>(out);
    mlp_kernel<<<B*M/8, 128>>>(pos, norm, W1, W2, b2, out);
}

// round 8
// speedup vs baseline: 1.2675x; 1.1805x over previous
#include <cuda_runtime.h>
#include <math.h>
#include <stdint.h>

#define B    8
#define N    4096
#define F    64
#define M    2048
#define KNB  32
#define H1   64
#define H2   128
#define R2   0.04f
#define CAP2 256

#define OUT_OFF   0
#define POSS_OFF  (B*M*H2)             // 2097152
#define NORMS_OFF (POSS_OFF + B*M*3)   // 2146304

// ---------------- scratch (no allocations allowed) ----------------
__device__ int    g_idx[B*M];
__device__ float  g_y[(size_t)B*N*H1];
__device__ int    g_nbr[B*M*KNB];
__device__ int    g_cnt[B*M];
__device__ float4 g_p4[B*N];

// ---------------- packed f32x2 helpers (sm_103a) ----------------
__device__ __forceinline__ uint64_t pk2(float lo, float hi) {
    uint64_t r;
    asm("mov.b64 %0, {%1, %2};" : "=l"(r)
        : "r"(__float_as_uint(lo)), "r"(__float_as_uint(hi)));
    return r;
}
__device__ __forceinline__ void upk2(float& lo, float& hi, uint64_t v) {
    unsigned a, b;
    asm("mov.b64 {%0, %1}, %2;" : "=r"(a), "=r"(b) : "l"(v));
    lo = __uint_as_float(a); hi = __uint_as_float(b);
}
__device__ __forceinline__ uint64_t add2(uint64_t a, uint64_t b) {
    uint64_t d; asm("add.rn.f32x2 %0, %1, %2;" : "=l"(d) : "l"(a), "l"(b)); return d;
}
__device__ __forceinline__ uint64_t mul2(uint64_t a, uint64_t b) {
    uint64_t d; asm("mul.rn.f32x2 %0, %1, %2;" : "=l"(d) : "l"(a), "l"(b)); return d;
}
__device__ __forceinline__ uint64_t fma2(uint64_t a, uint64_t b, uint64_t c) {
    uint64_t d; asm("fma.rn.f32x2 %0, %1, %2, %3;" : "=l"(d) : "l"(a), "l"(b), "l"(c)); return d;
}

// FROZEN exact-order |p|^2 (XLA uncontracted emission).
__device__ __forceinline__ float sum3sq_exact(float x, float y, float z)
{
    float a = __fmul_rn(x, x);
    float b = __fmul_rn(y, y);
    float c = __fmul_rn(z, z);
    return __fadd_rn(__fadd_rn(a, b), c);
}

// spread 3 bits to positions 0,3,6
__device__ __forceinline__ unsigned part3(unsigned v) {
    return (v & 1u) | ((v & 2u) << 2) | ((v & 4u) << 4);
}

// =============================================================
// Kernel: FPS. 8x8x8 Morton-ordered counting sort -> per-thread
// 8 contiguous points (tight bbox). Skip test
// mindist(bbox,c)^2*0.999 > threadmax guarantees every skipped
// dmin update is a no-op -> bit-identical to unpruned version.
// f32x2 distance math (validated bit-exact, R5 pass): per lane
// px + (-lx) == px - lx, separate mul/add in XLA order.
// =============================================================
extern "C" __global__ void __launch_bounds__(512, 1)
fps_kernel(const float* __restrict__ pos)
{
    extern __shared__ float fsm[];
    float* spx  = fsm;               // N
    float* spy  = fsm + N;           // N
    float* spz  = fsm + 2*N;         // N
    int*   sidx = (int*)(fsm + 3*N); // N
    __shared__ int hist[512];
    __shared__ int offs[512];
    __shared__ unsigned s_wval[2][16];
    __shared__ unsigned s_wpay[2][16];

    const int b = blockIdx.x;
    const float* pb = pos + (size_t)b*N*3;
    const int t = threadIdx.x;
    const int lane = t & 31, wid = t >> 5;

    hist[t] = 0;
    __syncthreads();
    for (int i = t; i < N; i += 512) {
        float x = pb[3*i], y = pb[3*i+1], z = pb[3*i+2];
        unsigned cx = min(7, (int)(x*8.0f));
        unsigned cy = min(7, (int)(y*8.0f));
        unsigned cz = min(7, (int)(z*8.0f));
        unsigned cell = part3(cx) | (part3(cy) << 1) | (part3(cz) << 2);
        atomicAdd(&hist[cell], 1);
    }
    __syncthreads();
    if (t == 0) {
        int run = 0;
        for (int c = 0; c < 512; c++) { offs[c] = run; run += hist[c]; }
    }
    __syncthreads();
    for (int i = t; i < N; i += 512) {
        float x = pb[3*i], y = pb[3*i+1], z = pb[3*i+2];
        unsigned cx = min(7, (int)(x*8.0f));
        unsigned cy = min(7, (int)(y*8.0f));
        unsigned cz = min(7, (int)(z*8.0f));
        unsigned cell = part3(cx) | (part3(cy) << 1) | (part3(cz) << 2);
        int slot = atomicAdd(&offs[cell], 1);
        spx[slot] = x; spy[slot] = y; spz[slot] = z; sidx[slot] = i;
    }
    if (t == 0) g_idx[b*M] = 0;
    __syncthreads();

    // thread-local 8 points: packed pairs + scalars for bbox
    const int base = 8*t;
    uint64_t PX[4], PY[4], PZ[4];
    {
        ulonglong2 xa = reinterpret_cast<const ulonglong2*>(spx)[2*t];
        ulonglong2 xb = reinterpret_cast<const ulonglong2*>(spx)[2*t+1];
        ulonglong2 ya = reinterpret_cast<const ulonglong2*>(spy)[2*t];
        ulonglong2 yb = reinterpret_cast<const ulonglong2*>(spy)[2*t+1];
        ulonglong2 za = reinterpret_cast<const ulonglong2*>(spz)[2*t];
        ulonglong2 zb = reinterpret_cast<const ulonglong2*>(spz)[2*t+1];
        PX[0]=xa.x; PX[1]=xa.y; PX[2]=xb.x; PX[3]=xb.y;
        PY[0]=ya.x; PY[1]=ya.y; PY[2]=yb.x; PY[3]=yb.y;
        PZ[0]=za.x; PZ[1]=za.y; PZ[2]=zb.x; PZ[3]=zb.y;
    }
    float dmin[8];
    unsigned pidx[8];
#pragma unroll
    for (int u = 0; u < 8; u++) {
        dmin[u] = 3.4e38f;
        pidx[u] = (((unsigned)sidx[base+u]) << 12) | (unsigned)(base + u);
    }
    float blx, bhx, bly, bhy, blz, bhz;
    {
        float a0, a1;
        upk2(a0, a1, PX[0]); blx = fminf(a0,a1); bhx = fmaxf(a0,a1);
        upk2(a0, a1, PY[0]); bly = fminf(a0,a1); bhy = fmaxf(a0,a1);
        upk2(a0, a1, PZ[0]); blz = fminf(a0,a1); bhz = fmaxf(a0,a1);
#pragma unroll
        for (int q = 1; q < 4; q++) {
            upk2(a0, a1, PX[q]); blx = fminf(blx, fminf(a0,a1)); bhx = fmaxf(bhx, fmaxf(a0,a1));
            upk2(a0, a1, PY[q]); bly = fminf(bly, fminf(a0,a1)); bhy = fmaxf(bhy, fmaxf(a0,a1));
            upk2(a0, a1, PZ[q]); blz = fminf(blz, fminf(a0,a1)); bhz = fmaxf(bhz, fmaxf(a0,a1));
        }
    }

    float lx = pb[0], ly = pb[1], lz = pb[2];
    float tmaxf = 3.4e38f;
    unsigned tbits = 0u, tpay = 0xffffffffu;
    int p = 0;

    for (int i = 1; i < M; i++) {
        float ddx = fmaxf(fmaxf(blx - lx, lx - bhx), 0.0f);
        float ddy = fmaxf(fmaxf(bly - ly, ly - bhy), 0.0f);
        float ddz = fmaxf(fmaxf(blz - lz, lz - bhz), 0.0f);
        float m2  = ddx*ddx + ddy*ddy + ddz*ddz;
        if (!(m2 * 0.999f > tmaxf)) {
            const uint64_t nlx = pk2(-lx, -lx);
            const uint64_t nly = pk2(-ly, -ly);
            const uint64_t nlz = pk2(-lz, -lz);
#pragma unroll
            for (int q = 0; q < 4; q++) {
                uint64_t dx = add2(PX[q], nlx);
                uint64_t dy = add2(PY[q], nly);
                uint64_t dz = add2(PZ[q], nlz);
                uint64_t s  = add2(add2(mul2(dx,dx), mul2(dy,dy)), mul2(dz,dz));
                float d0, d1; upk2(d0, d1, s);
                dmin[2*q]   = fminf(dmin[2*q],   d0);
                dmin[2*q+1] = fminf(dmin[2*q+1], d1);
            }
            // fmax tree + tie scan (min original index)
            float m01 = fmaxf(dmin[0], dmin[1]);
            float m23 = fmaxf(dmin[2], dmin[3]);
            float m45 = fmaxf(dmin[4], dmin[5]);
            float m67 = fmaxf(dmin[6], dmin[7]);
            float tm  = fmaxf(fmaxf(m01, m23), fmaxf(m45, m67));
            unsigned pay = 0xffffffffu;
#pragma unroll
            for (int u = 0; u < 8; u++)
                if (dmin[u] == tm) pay = min(pay, pidx[u]);
            tmaxf = tm;
            tbits = __float_as_uint(tm);
            tpay  = pay;
        }
        // warp argmax (max dbits, then min original-index payload)
        unsigned wmax = __reduce_max_sync(0xffffffffu, tbits);
        unsigned pc   = (tbits == wmax) ? tpay : 0xffffffffu;
        unsigned wpay = __reduce_min_sync(0xffffffffu, pc);
        if (lane == 0) { s_wval[p][wid] = wmax; s_wpay[p][wid] = wpay; }
        __syncthreads();
        unsigned v   = (lane < 16) ? s_wval[p][lane] : 0u;
        unsigned pv  = (lane < 16) ? s_wpay[p][lane] : 0xffffffffu;
        unsigned gm  = __reduce_max_sync(0xffffffffu, v);
        unsigned gpc = (v == gm) ? pv : 0xffffffffu;
        unsigned gp  = __reduce_min_sync(0xffffffffu, gpc);
        int slot = (int)(gp & 0xfffu);
        lx = spx[slot]; ly = spy[slot]; lz = spz[slot];
        if (t == 0) g_idx[b*M + i] = (int)(gp >> 12);
        p ^= 1;
    }
}

// =============================================================
// y = x @ W1[:64] + b1, split into two launches (row0 offset)
// so fps lands at profile-captured launch index 3.
// =============================================================
extern "C" __global__ void __launch_bounds__(256)
y_kernel(const float* __restrict__ x, const float* __restrict__ W1,
         const float* __restrict__ b1, int row0)
{
    __shared__ float W1s[64*64];
    __shared__ float xs[4][64];
    const int t = threadIdx.x;
    for (int i = t; i < 64*64; i += 256) W1s[i] = W1[i];
    const int g = t >> 6, c = t & 63;
    const int row = row0 + blockIdx.x*4 + g;
    xs[g][c] = x[(size_t)row*64 + c];
    __syncthreads();
    float acc = b1[c];
#pragma unroll 8
    for (int f = 0; f < 64; f++)
        acc = fmaf(xs[g][f], W1s[f*64 + c], acc);
    g_y[(size_t)row*64 + c] = acc;
}

extern "C" __global__ void p4_kernel(const float* __restrict__ pos)
{
    int i = blockIdx.x*256 + threadIdx.x;
    if (i >= B*N) return;
    float x = pos[3*i], y = pos[3*i+1], z = pos[3*i+2];
    g_p4[i] = make_float4(x, y, z, sum3sq_exact(x, y, z));
}

extern "C" __global__ void gather_kernel(const float* __restrict__ pos,
                                         const float* __restrict__ norm,
                                         float* __restrict__ outbuf)
{
    int i = blockIdx.x*256 + threadIdx.x;
    if (i >= B*M) return;
    int b = i / M;
    int j = g_idx[i];
    const float* p  = pos  + ((size_t)b*N + j)*3;
    const float* nr = norm + ((size_t)b*N + j)*3;
    outbuf[POSS_OFF  + i*3 + 0] = p[0];
    outbuf[POSS_OFF  + i*3 + 1] = p[1];
    outbuf[POSS_OFF  + i*3 + 2] = p[2];
    outbuf[NORMS_OFF + i*3 + 0] = nr[0];
    outbuf[NORMS_OFF + i*3 + 1] = nr[1];
    outbuf[NORMS_OFF + i*3 + 2] = nr[2];
}

// =============================================================
// neighbor selection (validated R6 form). FROZEN d2 order.
// =============================================================
extern "C" __global__ void __launch_bounds__(256)
select_kernel(const float* __restrict__ outbuf)
{
    extern __shared__ float ssm[];
    float* cd = ssm;
    int*   ci = (int*)(cd + 32*CAP2);
    __shared__ int scnt[32];

    const int t = threadIdx.x;
    const int w = t >> 5, lane = t & 31;
    const int gid0 = blockIdx.x*32 + w*4;
    const int b = gid0 / M;

    if (t < 32) scnt[t] = 0;
    __syncthreads();

    float cx[4], cy[4], cz[4], si[4];
#pragma unroll
    for (int c = 0; c < 4; c++) {
        int gid = gid0 + c;
        cx[c] = outbuf[POSS_OFF + gid*3 + 0];
        cy[c] = outbuf[POSS_OFF + gid*3 + 1];
        cz[c] = outbuf[POSS_OFF + gid*3 + 2];
        si[c] = sum3sq_exact(cx[c], cy[c], cz[c]);
    }
    const float4* pp = g_p4 + (size_t)b*N;

#pragma unroll 2
    for (int p = lane; p < N; p += 32) {
        float4 P = __ldg(&pp[p]);
#pragma unroll
        for (int c = 0; c < 4; c++) {
            float dot = __fadd_rn(__fadd_rn(__fmul_rn(cx[c], P.x),
                                            __fmul_rn(cy[c], P.y)),
                                  __fmul_rn(cz[c], P.z));
            float d2 = __fsub_rn(__fadd_rn(si[c], P.w), __fmul_rn(2.0f, dot));
            if (d2 <= R2) {
                int wc = w*4 + c;
                int slot = atomicAdd(&scnt[wc], 1);
                if (slot < CAP2) { cd[wc*CAP2 + slot] = d2; ci[wc*CAP2 + slot] = p; }
            }
        }
    }
    __syncwarp();

#pragma unroll 1
    for (int c = 0; c < 4; c++) {
        const int wc = w*4 + c;
        const int gid = gid0 + c;
        int cnt = scnt[wc]; if (cnt > CAP2) cnt = CAP2;
        float* mycd = cd + wc*CAP2;
        int*   myci = ci + wc*CAP2;

        if (cnt <= KNB) {
            for (int s = lane; s < cnt; s += 32)
                g_nbr[gid*KNB + s] = myci[s];
            if (lane == 0) g_cnt[gid] = cnt;
        } else {
            for (int r = 0; r < KNB; r++) {
                float bvv = 3.4e38f; int bslot = -1;
                for (int s = lane; s < cnt; s += 32) {
                    float v = mycd[s];
                    if (v < bvv) { bvv = v; bslot = s; }
                }
                unsigned wmin = __reduce_min_sync(0xffffffffu, __float_as_uint(bvv));
                int pidx = (__float_as_uint(bvv) == wmin && bslot >= 0)
                             ? myci[bslot] : 0x7fffffff;
                int widx = (int)__reduce_min_sync(0xffffffffu, (unsigned)pidx);
                if (pidx == widx && bslot >= 0) mycd[bslot] = 3.4e38f;
                if (lane == 0) g_nbr[gid*KNB + r] = widx;
                __syncwarp();
            }
            if (lane == 0) g_cnt[gid] = KNB;
        }
    }
}

// =============================================================
// fused PPF + layer1-residual + layer2 + masked max (validated)
// =============================================================
__device__ __forceinline__ float get_angle(float ax, float ay, float az,
                                           float bx, float by, float bz)
{
    float cxv = ay*bz - az*by;
    float cyv = az*bx - ax*bz;
    float czv = ax*by - ay*bx;
    float cn  = sqrtf(cxv*cxv + cyv*cyv + czv*czv);
    float d   = ax*bx + ay*by + az*bz;
    if (cn == 0.0f && d == 0.0f) d = 1.0f;
    return atan2f(cn, d);
}

extern "C" __global__ void __launch_bounds__(128)
mlp_kernel(const float* __restrict__ pos, const float* __restrict__ norm,
           const float* __restrict__ W1, const float* __restrict__ W2,
           const float* __restrict__ b2, float* __restrict__ outbuf)
{
    __shared__ float W2s[64*128];
    __shared__ float b2s[128];
    __shared__ float W1bs[4*64];
    __shared__ float h1t[64*34];
    __shared__ float pm[4*128];
    __shared__ int   snbr[32];
    __shared__ int   scnt_s;
    __shared__ float scen[6];

    const int t = threadIdx.x;
    for (int i = t; i < 64*128; i += 128) W2s[i] = W2[i];
    b2s[t & 127] = b2[t & 127];
    for (int i = t; i < 256; i += 128) W1bs[i] = W1[64*64 + i];

    for (int cblk = 0; cblk < 8; cblk++) {
        const int gid = blockIdx.x*8 + cblk;
        const int b = gid / M;
        __syncthreads();
        if (t < 32) snbr[t] = g_nbr[gid*KNB + t];
        if (t == 32) scnt_s = g_cnt[gid];
        if (t >= 40 && t < 43) scen[t-40]     = outbuf[POSS_OFF  + gid*3 + (t-40)];
        if (t >= 43 && t < 46) scen[3 + t-43] = outbuf[NORMS_OFF + gid*3 + (t-43)];
        __syncthreads();
        const int cnt = scnt_s;

        {
            const int k = t >> 2, q = t & 3;
            const int j = (k < cnt) ? snbr[k] : 0;
            const float* pj = pos  + ((size_t)b*N + j)*3;
            const float* nj = norm + ((size_t)b*N + j)*3;
            float px = pj[0], py = pj[1], pz = pj[2];
            float nx = nj[0], ny = nj[1], nz = nj[2];
            float cxp = scen[0], cyp = scen[1], czp = scen[2];
            float nix = scen[3], niy = scen[4], niz = scen[5];
            float dx = px - cxp, dy = py - cyp, dz = pz - czp;
            float f0 = sqrtf(dx*dx + dy*dy + dz*dz);
            float f1 = get_angle(nix, niy, niz, dx, dy, dz);
            float f2 = get_angle(nx,  ny,  nz,  dx, dy, dz);
            float f3 = get_angle(nix, niy, niz, nx, ny, nz);
            const float* yrow = g_y + ((size_t)b*N + j)*64 + q*16;
#pragma unroll
            for (int u = 0; u < 16; u++) {
                int f = q*16 + u;
                float v = yrow[u];
                v = fmaf(f0, W1bs[f],       v);
                v = fmaf(f1, W1bs[64  + f], v);
                v = fmaf(f2, W1bs[128 + f], v);
                v = fmaf(f3, W1bs[192 + f], v);
                h1t[f*34 + k] = fmaxf(v, 0.0f);
            }
        }
        __syncthreads();

        {
            const int kq = t >> 5, cg = t & 31;
            uint64_t accp[4][4];
#pragma unroll
            for (int ep = 0; ep < 4; ep++)
#pragma unroll
                for (int c = 0; c < 4; c++) accp[ep][c] = 0ull;

#pragma unroll 2
            for (int f = 0; f < 64; f++) {
                const float* hb = &h1t[f*34 + kq*8];
                uint64_t h0 = *reinterpret_cast<const uint64_t*>(hb + 0);
                uint64_t h1 = *reinterpret_cast<const uint64_t*>(hb + 2);
                uint64_t h2 = *reinterpret_cast<const uint64_t*>(hb + 4);
                uint64_t h3 = *reinterpret_cast<const uint64_t*>(hb + 6);
                float4 wv = *reinterpret_cast<const float4*>(&W2s[f*128 + cg*4]);
                uint64_t w0 = pk2(wv.x, wv.x);
                uint64_t w1 = pk2(wv.y, wv.y);
                uint64_t w2 = pk2(wv.z, wv.z);
                uint64_t w3 = pk2(wv.w, wv.w);
                accp[0][0] = fma2(h0, w0, accp[0][0]);
                accp[0][1] = fma2(h0, w1, accp[0][1]);
                accp[0][2] = fma2(h0, w2, accp[0][2]);
                accp[0][3] = fma2(h0, w3, accp[0][3]);
                accp[1][0] = fma2(h1, w0, accp[1][0]);
                accp[1][1] = fma2(h1, w1, accp[1][1]);
                accp[1][2] = fma2(h1, w2, accp[1][2]);
                accp[1][3] = fma2(h1, w3, accp[1][3]);
                accp[2][0] = fma2(h2, w0, accp[2][0]);
                accp[2][1] = fma2(h2, w1, accp[2][1]);
                accp[2][2] = fma2(h2, w2, accp[2][2]);
                accp[2][3] = fma2(h2, w3, accp[2][3]);
                accp[3][0] = fma2(h3, w0, accp[3][0]);
                accp[3][1] = fma2(h3, w1, accp[3][1]);
                accp[3][2] = fma2(h3, w2, accp[3][2]);
                accp[3][3] = fma2(h3, w3, accp[3][3]);
            }
            float v0 = -3.4e38f, v1 = -3.4e38f, v2 = -3.4e38f, v3 = -3.4e38f;
#pragma unroll
            for (int ep = 0; ep < 4; ep++) {
                const int e0 = kq*8 + 2*ep;
                float a, bb;
                upk2(a, bb, accp[ep][0]);
                if (e0     < cnt) v0 = fmaxf(v0, a);
                if (e0 + 1 < cnt) v0 = fmaxf(v0, bb);
                upk2(a, bb, accp[ep][1]);
                if (e0     < cnt) v1 = fmaxf(v1, a);
                if (e0 + 1 < cnt) v1 = fmaxf(v1, bb);
                upk2(a, bb, accp[ep][2]);
                if (e0     < cnt) v2 = fmaxf(v2, a);
                if (e0 + 1 < cnt) v2 = fmaxf(v2, bb);
                upk2(a, bb, accp[ep][3]);
                if (e0     < cnt) v3 = fmaxf(v3, a);
                if (e0 + 1 < cnt) v3 = fmaxf(v3, bb);
            }
            *reinterpret_cast<float4*>(&pm[kq*128 + cg*4]) =
                make_float4(v0, v1, v2, v3);
        }
        __syncthreads();

        {
            const int c = t;
            float v = fmaxf(fmaxf(pm[c], pm[128 + c]),
                            fmaxf(pm[256 + c], pm[384 + c]));
            float r = fmaxf(v + b2s[c], 0.0f);
            outbuf[(size_t)gid*128 + c] = r;
        }
    }
}

// =============================================================
extern "C" void kernel_launch(void* const* d_in, const int* in_sizes, int n_in,
                              void* d_out, int out_size)
{
    const float* x    = (const float*)d_in[0];
    const float* pos  = (const float*)d_in[1];
    const float* norm = (const float*)d_in[2];
    const float* W1   = (const float*)d_in[3];
    const float* b1   = (const float*)d_in[4];
    const float* W2   = (const float*)d_in[5];
    const float* b2   = (const float*)d_in[6];
    float* out = (float*)d_out;

    (void)in_sizes; (void)n_in; (void)out_size;

    cudaFuncSetAttribute(fps_kernel,
        cudaFuncAttributeMaxDynamicSharedMemorySize, 4*N*4);
    cudaFuncSetAttribute(select_kernel,
        cudaFuncAttributeMaxDynamicSharedMemorySize, 32*CAP2*8);

    // launch order chosen so fps_kernel is capture index 3 (ncu)
    y_kernel<<<B*N/8, 256>>>(x, W1, b1, 0);
    y_kernel<<<B*N/8, 256>>>(x, W1, b1, B*N/2);
    p4_kernel<<<(B*N + 255)/256, 256>>>(pos);
    fps_kernel<<<B, 512, 4*N*4>>>(pos);
    gather_kernel<<<(B*M + 255)/256, 256>>>(pos, norm, out);
    select_kernel<<<B*M/32, 256, 32*CAP2*8>>>(out);
    mlp_kernel<<<B*M/8, 128>>>(pos, norm, W1, W2, b2, out);
}